// round 5
// baseline (speedup 1.0000x reference)
#include <cuda_runtime.h>
#include <stdint.h>

// SpikeFP32Floor, round 5: 8 quads/thread as 4 software-pipelined pairs.
// Same proven bit logic as R2/R4; MLP_p1 = 2 (front pair only); loads of the
// next pair are issued before the stores of the current pair so there are
// always >=2 loads in flight without front-batching 4+ (which R3 showed
// creates L1tex-queue contention, not speedup).
//
// Layout per 32-quad batch: lane L loads float4 #(base+L); batch covers
// 512B = 4 fp32 values. group g = L/8 picks the value, slot s = L%8 picks
// MSB-first bit offsets 4s..4s+3. Nibble -> position 28-4s -> OR-tree over
// the 8-lane group (shfl_xor 1,2,4). floor_bits branchless. Unpack via
// multiply bit-spread, (0-bit) & 0x3F800000 per component.

__device__ __forceinline__ unsigned quad_nib(float4 v) {
    unsigned n;
    n  = (__float_as_uint(v.x) >> 26) & 8u;
    n |= (__float_as_uint(v.y) >> 27) & 4u;
    n |= (__float_as_uint(v.z) >> 28) & 2u;
    n |= (__float_as_uint(v.w) >> 29) & 1u;
    return n;
}

__device__ __forceinline__ unsigned floor_bits(unsigned u) {
    unsigned sgn = u & 0x80000000u;
    unsigned e   = (u >> 23) & 0xFFu;
    int d = 150 - (int)e;
    unsigned shc  = (unsigned)max(0, min(d, 23));
    unsigned mask = (1u << shc) - 1u;
    unsigned t    = u & ~mask;
    bool hasfrac  = (u & mask) != 0u;
    unsigned tm1  = __float_as_uint(__uint_as_float(t) - 1.0f);
    unsigned r    = (sgn && hasfrac) ? tm1 : t;
    if (e < 127u) r = sgn ? 0xBF800000u : 0u;
    return r;
}

__device__ __forceinline__ float4 unpack_nib(unsigned r, unsigned sh) {
    unsigned nib = (r >> sh) & 0xFu;
    unsigned sp  = (nib * 0x00204081u) & 0x01010101u;
    float4 o;
    o.x = __uint_as_float((0u - ((sp >> 24) & 1u)) & 0x3F800000u);
    o.y = __uint_as_float((0u - ((sp >> 16) & 1u)) & 0x3F800000u);
    o.z = __uint_as_float((0u - ((sp >>  8) & 1u)) & 0x3F800000u);
    o.w = __uint_as_float((0u - ( sp        & 1u)) & 0x3F800000u);
    return o;
}

__device__ __forceinline__ unsigned or_tree8(unsigned w) {
    w |= __shfl_xor_sync(0xFFFFFFFFu, w, 1);
    w |= __shfl_xor_sync(0xFFFFFFFFu, w, 2);
    w |= __shfl_xor_sync(0xFFFFFFFFu, w, 4);
    return w;
}

__global__ void __launch_bounds__(256)
spike_floor_v7(const float4* __restrict__ x, float4* __restrict__ out,
               unsigned int nquads)
{
    const unsigned QPW = 256u;                  // quads per warp (8/thread)
    unsigned tid  = blockIdx.x * blockDim.x + threadIdx.x;
    unsigned lane = threadIdx.x & 31u;
    unsigned warp = tid >> 5;

    size_t base = (size_t)warp * QPW;
    if (base + QPW > (size_t)nquads) return;    // warp-uniform guard

    size_t q = base + lane;
    unsigned sh = 28u - 4u * (lane & 7u);

    // Prologue: pair 0 loads in flight.
    float4 a = __ldcs(&x[q]);
    float4 b = __ldcs(&x[q + 32u]);

    #pragma unroll
    for (int p = 0; p < 4; ++p) {
        unsigned wa = or_tree8(quad_nib(a) << sh);
        unsigned wb = or_tree8(quad_nib(b) << sh);

        float4 oa = unpack_nib(floor_bits(wa), sh);
        float4 ob = unpack_nib(floor_bits(wb), sh);

        size_t qs = q;                          // this pair's position
        if (p < 3) {                            // issue next pair's loads
            q += 64u;
            a = __ldcs(&x[q]);
            b = __ldcs(&x[q + 32u]);
        }

        __stcs(&out[qs],       oa);
        __stcs(&out[qs + 32u], ob);
    }
}

extern "C" void kernel_launch(void* const* d_in, const int* in_sizes, int n_in,
                              void* d_out, int out_size)
{
    const float4* x   = (const float4*)d_in[0];
    float4*       out = (float4*)d_out;

    unsigned n_elems = (unsigned)in_sizes[0];   // 2048*1024*32 floats
    unsigned nquads  = n_elems >> 2;            // float4 count
    unsigned threads_total = nquads >> 3;       // 8 quads per thread

    const int threads = 256;
    unsigned blocks = (threads_total + threads - 1) / threads;

    spike_floor_v7<<<blocks, threads>>>(x, out, nquads);
}